// round 9
// baseline (speedup 1.0000x reference)
#include <cuda_runtime.h>

// CausalGraphGenerator: the reference builds A = diag(v) per batch, so
// A_diff = A - A^T == 0 exactly (off-diag entries are v*0.0f; on-diag
// subtract bitwise-identical values). Therefore
//   adj[b,i,j] = (i==j) ? 0.0f : max(-h, 0.0f)
// Output [B=4, C=64, C=64] fp32 = 16384 elements = 64 KB.
//
// Structure: all 4096 threads store a zero float4; 7 of 8 warps per block
// exit with no load dependency. Lane 0 of warp 0 in each block issues the h
// load FIRST (overlapping its L2 latency with the store issue), then only in
// the h < 0 case (never for this dataset, but required for faithfulness)
// rewrites its block's own 4 KB slice. Slice-local fixup => no cross-block
// write races. Fixup loop kept rolled (#pragma unroll 1) to minimize regs
// and cold-I$ footprint.

static constexpr int C  = 64;        // channels
static constexpr int CC = C * C;     // 4096 elements per batch slab

__global__ void __launch_bounds__(256, 1)
causal_graph_fill_kernel(const float* __restrict__ h_ptr,
                         float* __restrict__ out) {
    const int q = blockIdx.x * 256 + threadIdx.x;   // float4 index; grid covers 4096 exactly

    // Issue the h load as early as possible (lane 0 only) so its latency
    // overlaps the zero-store issue below.
    float hval = 0.0f;
    if (threadIdx.x == 0) hval = __ldg(h_ptr);

    // Unconditional zero store — bitwise-correct final value for every
    // element when h >= 0.
    reinterpret_cast<float4*>(out)[q] = make_float4(0.0f, 0.0f, 0.0f, 0.0f);

    // Fixup: only if relu(-h) != 0 (h < 0). Rewrites this block's own slice.
    const float offdiag = fmaxf(-hval, 0.0f);
    if (threadIdx.x == 0 && offdiag != 0.0f) {
        __threadfence();
        const int base0 = blockIdx.x * 1024;
        #pragma unroll 1
        for (int t = 0; t < 256; ++t) {
            int base = base0 + t * 4;
            int r = base & (CC - 1);
            int i = r >> 6;
            int j = r & (C - 1);
            float4 v;
            v.x = (j + 0 == i) ? 0.0f : offdiag;
            v.y = (j + 1 == i) ? 0.0f : offdiag;
            v.z = (j + 2 == i) ? 0.0f : offdiag;
            v.w = (j + 3 == i) ? 0.0f : offdiag;
            reinterpret_cast<float4*>(out)[base >> 2] = v;
        }
    }
}

extern "C" void kernel_launch(void* const* d_in, const int* in_sizes, int n_in,
                              void* d_out, int out_size) {
    // Inputs (metadata order): X, w1, b1, w2, b2, h
    const float* h_ptr = (const float*)d_in[5];
    float* out = (float*)d_out;

    // out_size = 16384 floats; 16 blocks x 256 threads x float4 covers it exactly.
    causal_graph_fill_kernel<<<16, 256>>>(h_ptr, out);
}

// round 12
// speedup vs baseline: 1.0625x; 1.0625x over previous
#include <cuda_runtime.h>

// CausalGraphGenerator: the reference builds A = diag(v) per batch, so
// A_diff = A - A^T == 0 exactly (off-diag entries are v*0.0f; on-diag
// subtract bitwise-identical values). Therefore
//   adj[b,i,j] = (i==j) ? 0.0f : max(-h, 0.0f)
// Output [B=4, C=64, C=64] fp32 = 16384 elements = 64 KB.
//
// Best-measured structure (R8): all 4096 threads store a zero float4 and
// 7 of 8 warps per block exit immediately with no load dependency. One
// thread per block loads h; only in the h < 0 case (never for this dataset,
// but required for input-faithfulness) does it rewrite its block's own 4 KB
// slice with the off-diagonal value. Slice-local fixup => no cross-block
// write races. Kernel is pinned at the launch-overhead floor (~T_ovh);
// all pipes at 0%, so no further device-side lever exists.

static constexpr int C  = 64;        // channels
static constexpr int CC = C * C;     // 4096 elements per batch slab

__global__ void __launch_bounds__(256, 1)
causal_graph_fill_kernel(const float* __restrict__ h_ptr,
                         float* __restrict__ out) {
    const int q = blockIdx.x * 256 + threadIdx.x;   // float4 index; grid covers 4096 exactly

    // Phase 1: unconditional zero store — no dependency on h. Bitwise-correct
    // final value for every element when h >= 0.
    reinterpret_cast<float4*>(out)[q] = make_float4(0.0f, 0.0f, 0.0f, 0.0f);

    // Phase 2: one thread per block checks h and, if relu(-h) != 0, rewrites
    // this block's own 256-float4 slice with position-determined constants.
    if (threadIdx.x == 0) {
        const float offdiag = fmaxf(-__ldg(h_ptr), 0.0f);
        if (offdiag != 0.0f) {
            __threadfence();   // order after phase-1 zeros
            int base0 = blockIdx.x * 1024;
            for (int t = 0; t < 256; ++t) {
                int base = base0 + t * 4;
                int r = base & (CC - 1);
                int i = r >> 6;
                int j = r & (C - 1);
                float4 v;
                v.x = (j + 0 == i) ? 0.0f : offdiag;
                v.y = (j + 1 == i) ? 0.0f : offdiag;
                v.z = (j + 2 == i) ? 0.0f : offdiag;
                v.w = (j + 3 == i) ? 0.0f : offdiag;
                reinterpret_cast<float4*>(out)[base >> 2] = v;
            }
        }
    }
}

extern "C" void kernel_launch(void* const* d_in, const int* in_sizes, int n_in,
                              void* d_out, int out_size) {
    // Inputs (metadata order): X, w1, b1, w2, b2, h
    const float* h_ptr = (const float*)d_in[5];
    float* out = (float*)d_out;

    // out_size = 16384 floats; 16 blocks x 256 threads x float4 covers it exactly.
    causal_graph_fill_kernel<<<16, 256>>>(h_ptr, out);
}